// round 17
// baseline (speedup 1.0000x reference)
#include <cuda_runtime.h>
#include <cstdint>

#define T_LEN 1024
#define B_SZ  128
#define D_IN  32
#define H_DIM 64
#define W_DIM 128
#define C_DIM 33     // D_IN + 1
#define O_DIM 2112   // H_DIM * C_DIM
#define O_MAIN 2048  // main (uniform) part of layer-3 outputs
#define BA    2      // batches per CTA
#define NCTA  (B_SZ / BA)   // 64
#define NTHR  256
#define NCHUNK 32          // 128 k / 4 k per chunk
#define CHUNK_FLOATS 8192  // 4 k rows * 2048 outputs
#define CHUNK_BYTES  32768

// Transposed copy of vW2 rows [0, 2048): g_vW2T[k * 2048 + o] = vW2[o * 128 + k]
__device__ float g_vW2T[W_DIM * O_MAIN];

__global__ void cde_transpose_kernel(const float* __restrict__ vW2) {
    int idx = blockIdx.x * blockDim.x + threadIdx.x;
    if (idx < W_DIM * O_MAIN) {
        int k = idx >> 11;     // / 2048
        int o = idx & 2047;
        g_vW2T[idx] = vW2[o * W_DIM + k];
    }
}

typedef unsigned long long u64;

struct __align__(16) Smem {
    float wstage[3][CHUNK_FLOATS];  // 98304 B cp.async weight ring (16B-aligned, first)
    float vW0p[W_DIM * 66];   // [j][paired w[1..64]]; stride 66 -> LDS.64 conflict-free
    float vW0c[W_DIM];        // w[j][0] (the t column)
    float vW1[W_DIM * 130];   // [j][k], stride 130 -> LDS.64 conflict-free
    float vb0[W_DIM];
    float vb1[W_DIM];
    float vb2[O_DIM];
    float vbuf[BA][O_DIM];    // v (tanh outputs), per batch
    float z1[BA][W_DIM];
    float z2[BA][W_DIM];
    float yhat1[BA][H_DIM];
    float dxv[BA][C_DIM];
    float cury[BA][D_IN];
    float red[BA][H_DIM];
};

__device__ __forceinline__ void ffma2(u64& d, u64 a, u64 b) {
    // d.lo += a.lo*b.lo ; d.hi += a.hi*b.hi  (packed fp32x2 FMA, sm_100+)
    asm("fma.rn.f32x2 %0, %1, %2, %0;" : "+l"(d) : "l"(a), "l"(b));
}
__device__ __forceinline__ u64 pack2(float x, float y) {
    u64 r;
    asm("mov.b64 %0, {%1, %2};" : "=l"(r) : "f"(x), "f"(y));
    return r;
}
__device__ __forceinline__ float2 unpack2(u64 v) {
    float2 r;
    asm("mov.b64 {%0, %1}, %2;" : "=f"(r.x), "=f"(r.y) : "l"(v));
    return r;
}
__device__ __forceinline__ uint32_t s2u(const void* p) {
    uint32_t a;
    asm("{ .reg .u64 t; cvta.to.shared.u64 t, %1; cvt.u32.u64 %0, t; }" : "=r"(a) : "l"(p));
    return a;
}
__device__ __forceinline__ void cp16(uint32_t dst, const float* __restrict__ src) {
    asm volatile("cp.async.cg.shared.global [%0], [%1], 16;" :: "r"(dst), "l"(src) : "memory");
}

__device__ __forceinline__ float lipswish_f(float x) {
    float sg = __fdividef(1.0f, 1.0f + __expf(-x));
    return 0.909f * x * sg;
}
__device__ __forceinline__ float tanh_f(float x) {
    float e = __expf(2.0f * x);
    return 1.0f - __fdividef(2.0f, e + 1.0f);
}

// Stage chunk c (k rows 4c..4c+3) of g_vW2T into ring slot; each thread copies ONLY
// the 2x16B it will consume. One commit_group per chunk.
__device__ __forceinline__ void stage_chunk(uint32_t wsu, int slot, int c, int t4) {
    uint32_t base = wsu + (uint32_t)slot * CHUNK_BYTES + (uint32_t)t4 * 4;
    const float* src = g_vW2T + (size_t)(4 * c) * O_MAIN + t4;
    #pragma unroll
    for (int u = 0; u < 4; u++) {
        cp16(base + u * 8192u, src);
        cp16(base + u * 8192u + 4096u, src + 1024);
        src += O_MAIN;
    }
    asm volatile("cp.async.commit_group;" ::: "memory");
}

// Consume staged chunk ch from ring slot (thread-private data; no sync needed).
__device__ __forceinline__ void consume_chunk(Smem* sm, int ch, int slot, int t4, u64* acc) {
    const float* ws = sm->wstage[slot];
    float4 zq0 = *(const float4*)&sm->z2[0][4 * ch];
    float4 zq1 = *(const float4*)&sm->z2[1][4 * ch];
    const float z0v[4] = {zq0.x, zq0.y, zq0.z, zq0.w};
    const float z1v[4] = {zq1.x, zq1.y, zq1.z, zq1.w};
    #pragma unroll
    for (int u = 0; u < 4; u++) {
        ulonglong2 wa = *(const ulonglong2*)&ws[u * 2048 + t4];
        ulonglong2 wb = *(const ulonglong2*)&ws[u * 2048 + 1024 + t4];
        u64 zz0 = pack2(z0v[u], z0v[u]);
        u64 zz1 = pack2(z1v[u], z1v[u]);
        ffma2(acc[0], wa.x, zz0); ffma2(acc[1], wa.y, zz0);
        ffma2(acc[2], wb.x, zz0); ffma2(acc[3], wb.y, zz0);
        ffma2(acc[4], wa.x, zz1); ffma2(acc[5], wa.y, zz1);
        ffma2(acc[6], wb.x, zz1); ffma2(acc[7], wb.y, zz1);
    }
}

// vbuf = tanh(vW2 @ lipswish(vW1 @ lipswish(vW0 @ [t, yhat1] + vb0) + vb1) + vb2)
// for both batches. 256 threads. Layer-3 weights flow through the cp.async ring.
__device__ __forceinline__ void vf_eval(Smem* sm, int tid, float t1,
                                        const float* __restrict__ vW2) {
    const int bb = tid >> 7;
    const int j  = tid & 127;
    const int t4 = 4 * tid;
    const uint32_t wsu = s2u(sm->wstage);

    // Prologue: start streaming chunks 0,1 now; they land during layers 1-2.
    stage_chunk(wsu, 0, 0, t4);
    stage_chunk(wsu, 1, 1, t4);

    // ---- layer 1: (65 -> 128), paired FFMA2 over the 64 yh inputs ----
    {
        const u64* wp = (const u64*)&sm->vW0p[j * 66];
        const u64* yp = (const u64*)sm->yhat1[bb];
        u64 acc[4] = {0ull, 0ull, 0ull, 0ull};
        #pragma unroll
        for (int p = 0; p < 32; p++) ffma2(acc[p & 3], wp[p], yp[p]);
        float2 s0 = unpack2(acc[0]), s1 = unpack2(acc[1]);
        float2 s2 = unpack2(acc[2]), s3 = unpack2(acc[3]);
        float a = sm->vb0[j] + t1 * sm->vW0c[j]
                + ((s0.x + s0.y) + (s1.x + s1.y))
                + ((s2.x + s2.y) + (s3.x + s3.y));
        sm->z1[bb][j] = lipswish_f(a);
    }
    __syncthreads();

    // ---- layer 2: (128 -> 128), paired ----
    {
        const u64* wp = (const u64*)&sm->vW1[j * 130];
        const u64* zp = (const u64*)sm->z1[bb];
        u64 acc[4] = {0ull, 0ull, 0ull, 0ull};
        #pragma unroll
        for (int p = 0; p < 64; p++) ffma2(acc[p & 3], wp[p], zp[p]);
        float2 s0 = unpack2(acc[0]), s1 = unpack2(acc[1]);
        float2 s2 = unpack2(acc[2]), s3 = unpack2(acc[3]);
        float a = sm->vb1[j]
                + ((s0.x + s0.y) + (s1.x + s1.y))
                + ((s2.x + s2.y) + (s3.x + s3.y));
        sm->z2[bb][j] = lipswish_f(a);
    }
    __syncthreads();

    // ---- layer 3 main: outputs [0, 2048), 8 per thread x 2 batches,
    //      weights via 3-slot cp.async ring (thread-local sync only) ----
    {
        u64 acc[8];
        #pragma unroll
        for (int i = 0; i < 8; i++) acc[i] = 0ull;

        #pragma unroll 2
        for (int ch = 0; ch < NCHUNK - 2; ch++) {
            stage_chunk(wsu, (ch + 2) % 3, ch + 2, t4);
            asm volatile("cp.async.wait_group 2;" ::: "memory");
            consume_chunk(sm, ch, ch % 3, t4, acc);
        }
        asm volatile("cp.async.wait_group 1;" ::: "memory");
        consume_chunk(sm, NCHUNK - 2, (NCHUNK - 2) % 3, t4, acc);
        asm volatile("cp.async.wait_group 0;" ::: "memory");
        consume_chunk(sm, NCHUNK - 1, (NCHUNK - 1) % 3, t4, acc);

        // epilogue: bias + tanh + store
        {
            int oa = 4 * tid, ob = 4 * tid + 1024;
            float2 r;
            r = unpack2(acc[0]);
            sm->vbuf[0][oa + 0] = tanh_f(r.x + sm->vb2[oa + 0]);
            sm->vbuf[0][oa + 1] = tanh_f(r.y + sm->vb2[oa + 1]);
            r = unpack2(acc[1]);
            sm->vbuf[0][oa + 2] = tanh_f(r.x + sm->vb2[oa + 2]);
            sm->vbuf[0][oa + 3] = tanh_f(r.y + sm->vb2[oa + 3]);
            r = unpack2(acc[2]);
            sm->vbuf[0][ob + 0] = tanh_f(r.x + sm->vb2[ob + 0]);
            sm->vbuf[0][ob + 1] = tanh_f(r.y + sm->vb2[ob + 1]);
            r = unpack2(acc[3]);
            sm->vbuf[0][ob + 2] = tanh_f(r.x + sm->vb2[ob + 2]);
            sm->vbuf[0][ob + 3] = tanh_f(r.y + sm->vb2[ob + 3]);
            r = unpack2(acc[4]);
            sm->vbuf[1][oa + 0] = tanh_f(r.x + sm->vb2[oa + 0]);
            sm->vbuf[1][oa + 1] = tanh_f(r.y + sm->vb2[oa + 1]);
            r = unpack2(acc[5]);
            sm->vbuf[1][oa + 2] = tanh_f(r.x + sm->vb2[oa + 2]);
            sm->vbuf[1][oa + 3] = tanh_f(r.y + sm->vb2[oa + 3]);
            r = unpack2(acc[6]);
            sm->vbuf[1][ob + 0] = tanh_f(r.x + sm->vb2[ob + 0]);
            sm->vbuf[1][ob + 1] = tanh_f(r.y + sm->vb2[ob + 1]);
            r = unpack2(acc[7]);
            sm->vbuf[1][ob + 2] = tanh_f(r.x + sm->vb2[ob + 2]);
            sm->vbuf[1][ob + 3] = tanh_f(r.y + sm->vb2[ob + 3]);
        }
    }

    // ---- layer 3 tail: outputs [2048, 2112), warp-per-output reduction over original vW2 ----
    {
        const int w = tid >> 5, lane = tid & 31;
        float4 zz0 = *(const float4*)&sm->z2[0][4 * lane];
        float4 zz1 = *(const float4*)&sm->z2[1][4 * lane];
        #pragma unroll
        for (int i = 0; i < 8; i++) {
            int o = O_MAIN + w * 8 + i;
            float4 wv = *(const float4*)(vW2 + (size_t)o * W_DIM + 4 * lane);
            float a0 = wv.x * zz0.x + wv.y * zz0.y + wv.z * zz0.z + wv.w * zz0.w;
            float a1 = wv.x * zz1.x + wv.y * zz1.y + wv.z * zz1.z + wv.w * zz1.w;
            #pragma unroll
            for (int off = 16; off; off >>= 1) {
                a0 += __shfl_xor_sync(0xffffffffu, a0, off);
                a1 += __shfl_xor_sync(0xffffffffu, a1, off);
            }
            if (lane == 0) {
                float b = sm->vb2[o];
                sm->vbuf[0][o] = tanh_f(a0 + b);
                sm->vbuf[1][o] = tanh_f(a1 + b);
            }
        }
    }
    __syncthreads();
}

__global__ void __launch_bounds__(NTHR, 1) cde_kernel(
    const float* __restrict__ ts,  const float* __restrict__ ys,
    const float* __restrict__ iW0, const float* __restrict__ ib0,
    const float* __restrict__ iW1, const float* __restrict__ ib1,
    const float* __restrict__ iW2, const float* __restrict__ ib2,
    const float* __restrict__ vW0, const float* __restrict__ vb0,
    const float* __restrict__ vW1, const float* __restrict__ vb1,
    const float* __restrict__ vW2, const float* __restrict__ vb2,
    const float* __restrict__ rW,  const float* __restrict__ rb,
    float* __restrict__ out)
{
    extern __shared__ float smraw[];
    Smem* sm = reinterpret_cast<Smem*>(smraw);
    const int tid = threadIdx.x;
    const int b0  = blockIdx.x * BA;   // two batch elements per CTA

    // ---- stage weights into smem (paired layouts) ----
    for (int i = tid; i < W_DIM * 65; i += NTHR) {
        int j = i / 65, c = i % 65;
        if (c == 0) sm->vW0c[j] = vW0[i];
        else        sm->vW0p[j * 66 + (c - 1)] = vW0[i];
    }
    for (int i = tid; i < W_DIM * W_DIM; i += NTHR) {
        int j = i >> 7, k = i & 127;
        sm->vW1[j * 130 + k] = vW1[i];
    }
    if (tid < W_DIM) { sm->vb0[tid] = vb0[tid]; sm->vb1[tid] = vb1[tid]; }
    for (int i = tid; i < O_DIM; i += NTHR) sm->vb2[i] = vb2[i];

    // initial input x0 = [ts[0], ys[b,0,:]]  (reuse dxv buffer)
    if (tid < BA * C_DIM) {
        int bb = tid / C_DIM, c = tid % C_DIM;
        sm->dxv[bb][c] = (c == 0) ? ts[0]
                                  : ys[(size_t)(b0 + bb) * T_LEN * D_IN + (c - 1)];
    }
    if (tid < BA * D_IN) {
        int bb = tid >> 5, c = tid & 31;
        sm->cury[bb][c] = ys[(size_t)(b0 + bb) * T_LEN * D_IN + c];
    }
    __syncthreads();

    // ---- initial MLP: relu(iW0 x + ib0) -> relu(iW1 . + ib1) -> iW2 . + ib2 ----
    {
        int bb = tid >> 7, j = tid & 127;
        float a = ib0[j];
        #pragma unroll
        for (int i = 0; i < C_DIM; i++) a += sm->dxv[bb][i] * iW0[j * C_DIM + i];
        sm->z1[bb][j] = fmaxf(a, 0.f);
    }
    __syncthreads();
    {
        int bb = tid >> 7, j = tid & 127;
        float a = ib1[j];
        #pragma unroll 8
        for (int k = 0; k < W_DIM; k++) a += sm->z1[bb][k] * iW1[j * W_DIM + k];
        sm->z2[bb][j] = fmaxf(a, 0.f);
    }
    __syncthreads();

    float y = 0.f, yhat = 0.f, sdot = 0.f;
    if (tid < BA * H_DIM) {
        int bb = tid >> 6, h = tid & 63;
        float a = ib2[h];
        #pragma unroll 8
        for (int k = 0; k < W_DIM; k++) a += sm->z2[bb][k] * iW2[h * W_DIM + k];
        y = a; yhat = a;
        sm->yhat1[bb][h] = a;
    }
    __syncthreads();

    // v0 = vf(ts[0], y0)
    vf_eval(sm, tid, ts[0], vW2);

    // ---- scan over 1023 steps ----
    float tprev = ts[0];
    for (int t = 1; t < T_LEN; t++) {
        float t1 = __ldg(&ts[t]);

        // dx = x[t] - x[t-1]
        if (tid < BA * C_DIM) {
            int bb = tid / C_DIM, c = tid % C_DIM;
            if (c == 0) {
                sm->dxv[bb][0] = t1 - tprev;
            } else {
                float nv = ys[(size_t)(b0 + bb) * T_LEN * D_IN + (size_t)t * D_IN + (c - 1)];
                sm->dxv[bb][c] = nv - sm->cury[bb][c - 1];
                sm->cury[bb][c - 1] = nv;
            }
        }
        tprev = t1;
        __syncthreads();

        // s = v . dx ; yhat1 = 2y - yhat + s
        if (tid < BA * H_DIM) {
            int bb = tid >> 6, h = tid & 63;
            const float* vp = &sm->vbuf[bb][h * C_DIM];
            const float* dp = sm->dxv[bb];
            float a = 0.f;
            #pragma unroll
            for (int c = 0; c < C_DIM; c++) a += vp[c] * dp[c];
            sdot = a;
            float yh1 = 2.f * y - yhat + a;
            yhat = yh1;
            sm->yhat1[bb][h] = yh1;
        }
        __syncthreads();

        // v1 = vf(t1, yhat1)  (overwrites vbuf)
        vf_eval(sm, tid, t1, vW2);

        // y += 0.5 * (s + v1 . dx)
        if (tid < BA * H_DIM) {
            int bb = tid >> 6, h = tid & 63;
            const float* vp = &sm->vbuf[bb][h * C_DIM];
            const float* dp = sm->dxv[bb];
            float a = 0.f;
            #pragma unroll
            for (int c = 0; c < C_DIM; c++) a += vp[c] * dp[c];
            y += 0.5f * (sdot + a);
        }
        __syncthreads();   // protects dxv/cury for next iteration's writes
    }

    // ---- readout: out[b] = y . rW + rb ----
    if (tid < BA * H_DIM) {
        int bb = tid >> 6, h = tid & 63;
        sm->red[bb][h] = y * rW[h];
    }
    __syncthreads();
    if (tid < BA) {
        float a = rb[0];
        #pragma unroll
        for (int h = 0; h < H_DIM; h++) a += sm->red[tid][h];
        out[b0 + tid] = a;
    }
}

extern "C" void kernel_launch(void* const* d_in, const int* in_sizes, int n_in,
                              void* d_out, int out_size) {
    (void)in_sizes; (void)n_in; (void)out_size;
    const float* ts  = (const float*)d_in[0];
    const float* ys  = (const float*)d_in[1];
    const float* iW0 = (const float*)d_in[2];
    const float* ib0 = (const float*)d_in[3];
    const float* iW1 = (const float*)d_in[4];
    const float* ib1 = (const float*)d_in[5];
    const float* iW2 = (const float*)d_in[6];
    const float* ib2 = (const float*)d_in[7];
    const float* vW0 = (const float*)d_in[8];
    const float* vb0 = (const float*)d_in[9];
    const float* vW1 = (const float*)d_in[10];
    const float* vb1 = (const float*)d_in[11];
    const float* vW2 = (const float*)d_in[12];
    const float* vb2 = (const float*)d_in[13];
    const float* rW  = (const float*)d_in[14];
    const float* rb  = (const float*)d_in[15];
    float* out = (float*)d_out;

    cudaFuncSetAttribute(cde_kernel, cudaFuncAttributeMaxDynamicSharedMemorySize,
                         (int)sizeof(Smem));

    cde_transpose_kernel<<<(W_DIM * O_MAIN + 255) / 256, 256>>>(vW2);
    cde_kernel<<<NCTA, NTHR, sizeof(Smem)>>>(
        ts, ys, iW0, ib0, iW1, ib1, iW2, ib2,
        vW0, vb0, vW1, vb1, vW2, vb2, rW, rb, out);
}